// round 12
// baseline (speedup 1.0000x reference)
#include <cuda_runtime.h>
#include <cuda_bf16.h>
#include <cstdint>

#define LSEQ   4096
#define HDIM   2048
#define NPROJ  12352
#define QKVZ_N 12288
#define KEY_DIM 2048
#define VAL_DIM 4096
#define NHV    32
#define DKC    128
#define DVC    128
#define NPAD1  12416
#define CHK    32
#define NCHK   128

__device__ float g_proj [(size_t)LSEQ * NPROJ];
__device__ float g_q    [(size_t)LSEQ * KEY_DIM];
__device__ float g_k    [(size_t)LSEQ * KEY_DIM];
__device__ float g_v    [(size_t)LSEQ * VAL_DIM];
__device__ float g_gdec [(size_t)LSEQ * NHV];   // raw g
__device__ float g_beta [(size_t)LSEQ * NHV];
__device__ float g_core [(size_t)LSEQ * VAL_DIM];

__device__ float g_u  [(size_t)NHV * NCHK * CHK * DKC];
__device__ float g_Wk [(size_t)NHV * NCHK * CHK * DKC];
__device__ float g_rk [(size_t)NHV * NCHK * CHK * DKC];
__device__ float g_Bq [(size_t)NHV * NCHK * CHK * CHK];
__device__ float g_P  [(size_t)NHV * NCHK * CHK];

__device__ __nv_bfloat16 g_hid_hi[(size_t)LSEQ * HDIM];
__device__ __nv_bfloat16 g_hid_lo[(size_t)LSEQ * HDIM];
__device__ __nv_bfloat16 g_w1_hi [(size_t)NPAD1 * HDIM];
__device__ __nv_bfloat16 g_w1_lo [(size_t)NPAD1 * HDIM];
__device__ __nv_bfloat16 g_gat_hi[(size_t)LSEQ * VAL_DIM];
__device__ __nv_bfloat16 g_gat_lo[(size_t)LSEQ * VAL_DIM];
__device__ __nv_bfloat16 g_w2_hi [(size_t)HDIM * VAL_DIM];
__device__ __nv_bfloat16 g_w2_lo [(size_t)HDIM * VAL_DIM];

__device__ __forceinline__ uint32_t smem_u32(const void* p) {
    uint32_t a;
    asm("{ .reg .u64 t; cvta.to.shared.u64 t, %1; cvt.u32.u64 %0, t; }"
        : "=r"(a) : "l"(p));
    return a;
}
#define SW64(x) ((x) ^ (((x) >> 3) & 0x30))
__device__ __forceinline__ void cpa16(uint32_t s, const void* g) {
    asm volatile("cp.async.cg.shared.global [%0], [%1], 16;" :: "r"(s), "l"(g));
}
__device__ __forceinline__ void cpa_commit() {
    asm volatile("cp.async.commit_group;" ::: "memory");
}
__device__ __forceinline__ void cpa_wait1() {
    asm volatile("cp.async.wait_group 1;" ::: "memory");
}
__device__ __forceinline__ void cpa_wait0() {
    asm volatile("cp.async.wait_group 0;" ::: "memory");
}
__device__ __forceinline__ void ldsm4(uint32_t& r0, uint32_t& r1, uint32_t& r2,
                                      uint32_t& r3, uint32_t a) {
    asm volatile("ldmatrix.sync.aligned.m8n8.x4.shared.b16 {%0,%1,%2,%3}, [%4];"
                 : "=r"(r0), "=r"(r1), "=r"(r2), "=r"(r3) : "r"(a));
}
__device__ __forceinline__ void mma16816(float* c, const uint32_t* a,
                                         const uint32_t* b) {
    asm volatile(
        "mma.sync.aligned.m16n8k16.row.col.f32.bf16.bf16.f32 "
        "{%0,%1,%2,%3}, {%4,%5,%6,%7}, {%8,%9}, {%0,%1,%2,%3};"
        : "+f"(c[0]), "+f"(c[1]), "+f"(c[2]), "+f"(c[3])
        : "r"(a[0]), "r"(a[1]), "r"(a[2]), "r"(a[3]), "r"(b[0]), "r"(b[1]));
}

// ---- packed f32x2 (Blackwell FFMA2 path) ----
__device__ __forceinline__ uint64_t fma2(uint64_t a, uint64_t b, uint64_t c) {
    uint64_t d;
    asm("fma.rn.f32x2 %0, %1, %2, %3;" : "=l"(d) : "l"(a), "l"(b), "l"(c));
    return d;
}
__device__ __forceinline__ uint64_t add2(uint64_t a, uint64_t b) {
    uint64_t d;
    asm("add.rn.f32x2 %0, %1, %2;" : "=l"(d) : "l"(a), "l"(b));
    return d;
}
__device__ __forceinline__ uint64_t mul2(uint64_t a, uint64_t b) {
    uint64_t d;
    asm("mul.rn.f32x2 %0, %1, %2;" : "=l"(d) : "l"(a), "l"(b));
    return d;
}
__device__ __forceinline__ uint64_t pack2(float x, float y) {
    uint64_t d;
    asm("mov.b64 %0, {%1, %2};" : "=l"(d) : "f"(x), "f"(y));
    return d;
}
__device__ __forceinline__ float2 unpack2(uint64_t v) {
    float x, y;
    asm("mov.b64 {%0, %1}, %2;" : "=f"(x), "=f"(y) : "l"(v));
    return make_float2(x, y);
}

// ---------------- bf16x3 mma.sync GEMM (unchanged) -----------------------------
#define GSTAGE 32768
#define NSTAGE 3
#define GEMM_SMEM (NSTAGE * GSTAGE)

__global__ __launch_bounds__(256, 2) void gemm_b3_kernel(
    const __nv_bfloat16* __restrict__ Ahi, const __nv_bfloat16* __restrict__ Alo,
    const __nv_bfloat16* __restrict__ Bhi, const __nv_bfloat16* __restrict__ Blo,
    float* __restrict__ C, int M, int N, int K)
{
    extern __shared__ char smem[];
    const uint32_t sb = smem_u32(smem);
    const int tid = threadIdx.x;
    const int wid = tid >> 5;
    const int lane = tid & 31;
    const int wm = wid >> 1;
    const int wn = wid & 1;
    const int bm = blockIdx.y * 128;
    const int bn = blockIdx.x * 128;
    const int rowh = tid >> 2;
    const int kc = tid & 3;
    const __nv_bfloat16* gp[4];
    gp[0] = Ahi + (size_t)bm * K;
    gp[1] = Alo + (size_t)bm * K;
    gp[2] = Bhi + (size_t)bn * K;
    gp[3] = Blo + (size_t)bn * K;

    float acc[2][8][4];
#pragma unroll
    for (int i = 0; i < 2; i++)
#pragma unroll
        for (int j = 0; j < 8; j++)
#pragma unroll
            for (int x = 0; x < 4; x++) acc[i][j][x] = 0.f;

    const int nk = K >> 5;
    uint32_t aoff[2][2], boff[4][2];
#pragma unroll
    for (int t = 0; t < 2; t++)
#pragma unroll
        for (int ks = 0; ks < 2; ks++)
            aoff[t][ks] = SW64(((wm * 32 + t * 16 + (lane & 15)) << 6)
                               + ks * 32 + ((lane >> 4) << 4));
#pragma unroll
    for (int p = 0; p < 4; p++)
#pragma unroll
        for (int ks = 0; ks < 2; ks++)
            boff[p][ks] = SW64(((wn * 64 + p * 16 + ((lane >> 4) << 3) + (lane & 7)) << 6)
                               + ks * 32 + (((lane >> 3) & 1) << 4)) + 16384;

#pragma unroll
    for (int s = 0; s < 2; s++) {
        const size_t k0 = (size_t)s << 5;
        const uint32_t stb = sb + s * GSTAGE;
#pragma unroll
        for (int j = 0; j < 8; j++) {
            const int tile = j >> 1;
            const int row = ((j & 1) << 6) + rowh;
            cpa16(stb + (tile << 13) + SW64((row << 6) + kc * 16),
                  gp[tile] + (size_t)row * K + k0 + kc * 8);
        }
        cpa_commit();
    }

    int sc = 0, sp = 2;
    for (int kt = 0; kt < nk; ++kt) {
        if (kt < nk - 1) cpa_wait1();
        else             cpa_wait0();
        __syncthreads();
        if (kt + 2 < nk) {
            const size_t k0 = (size_t)(kt + 2) << 5;
            const uint32_t stb = sb + sp * GSTAGE;
#pragma unroll
            for (int j = 0; j < 8; j++) {
                const int tile = j >> 1;
                const int row = ((j & 1) << 6) + rowh;
                cpa16(stb + (tile << 13) + SW64((row << 6) + kc * 16),
                      gp[tile] + (size_t)row * K + k0 + kc * 8);
            }
            cpa_commit();
        }
        const uint32_t base = sb + sc * GSTAGE;
        if (++sc == NSTAGE) sc = 0;
        if (++sp == NSTAGE) sp = 0;
#pragma unroll
        for (int ks = 0; ks < 2; ks++) {
            uint32_t ah[2][4], al[2][4], bh[8][2];
#pragma unroll
            for (int t = 0; t < 2; t++) {
                ldsm4(ah[t][0], ah[t][1], ah[t][2], ah[t][3], base + aoff[t][ks]);
                ldsm4(al[t][0], al[t][1], al[t][2], al[t][3], base + 8192 + aoff[t][ks]);
            }
#pragma unroll
            for (int p = 0; p < 4; p++)
                ldsm4(bh[2 * p][0], bh[2 * p][1], bh[2 * p + 1][0], bh[2 * p + 1][1],
                      base + boff[p][ks]);
#pragma unroll
            for (int i = 0; i < 2; i++)
#pragma unroll
                for (int j = 0; j < 8; j++)
                    mma16816(acc[i][j], ah[i], bh[j]);
#pragma unroll
            for (int i = 0; i < 2; i++)
#pragma unroll
                for (int j = 0; j < 8; j++)
                    mma16816(acc[i][j], al[i], bh[j]);
#pragma unroll
            for (int p = 0; p < 4; p++) {
                uint32_t bl0[2], bl1[2];
                ldsm4(bl0[0], bl0[1], bl1[0], bl1[1], base + 8192 + boff[p][ks]);
                mma16816(acc[0][2 * p],     ah[0], bl0);
                mma16816(acc[1][2 * p],     ah[1], bl0);
                mma16816(acc[0][2 * p + 1], ah[0], bl1);
                mma16816(acc[1][2 * p + 1], ah[1], bl1);
            }
        }
    }
#pragma unroll
    for (int i = 0; i < 2; i++) {
        const int r0 = bm + wm * 32 + i * 16 + (lane >> 2);
#pragma unroll
        for (int j = 0; j < 8; j++) {
            const int col = bn + wn * 64 + j * 8 + (lane & 3) * 2;
            if (col < N) {
                *(float2*)&C[(size_t)r0 * N + col] =
                    make_float2(acc[i][j][0], acc[i][j][1]);
                *(float2*)&C[(size_t)(r0 + 8) * N + col] =
                    make_float2(acc[i][j][2], acc[i][j][3]);
            }
        }
    }
}

// ---------------- conversions --------------------------------------------------
__global__ __launch_bounds__(256) void conv_hl_kernel(
    const float* __restrict__ X, __nv_bfloat16* __restrict__ hi,
    __nv_bfloat16* __restrict__ lo, size_t n)
{
    size_t i = (size_t)blockIdx.x * 256 + threadIdx.x;
    if (i < n) {
        float x = X[i];
        __nv_bfloat16 h = __float2bfloat16(x);
        hi[i] = h;
        lo[i] = __float2bfloat16(x - __bfloat162float(h));
    }
}

__global__ __launch_bounds__(256) void convT_kernel(
    const float* __restrict__ W, __nv_bfloat16* __restrict__ hi,
    __nv_bfloat16* __restrict__ lo, int K, int N)
{
    __shared__ float t[32][33];
    const int nb = blockIdx.x * 32;
    const int kb = blockIdx.y * 32;
    const int tx = threadIdx.x & 31;
    const int ty = threadIdx.x >> 5;
#pragma unroll
    for (int p = 0; p < 4; p++) {
        int r = ty + p * 8;
        int n = nb + tx;
        t[r][tx] = (n < N) ? W[(size_t)(kb + r) * N + n] : 0.f;
    }
    __syncthreads();
#pragma unroll
    for (int p = 0; p < 4; p++) {
        int r = ty + p * 8;
        float x = t[tx][r];
        __nv_bfloat16 h = __float2bfloat16(x);
        __nv_bfloat16 l = __float2bfloat16(x - __bfloat162float(h));
        size_t o = (size_t)(nb + r) * K + kb + tx;
        hi[o] = h;
        lo[o] = l;
    }
}

// ---------------- conv(K=4) + silu + l2norm + gating prep ----------------------
__global__ __launch_bounds__(256) void prep_kernel(
    const float* __restrict__ proj, const float* __restrict__ conv_w,
    const float* __restrict__ A_log, const float* __restrict__ dt_bias,
    float* __restrict__ qo, float* __restrict__ ko, float* __restrict__ vo,
    float* __restrict__ go, float* __restrict__ bo)
{
    const int l = blockIdx.x;
    const int tid = threadIdx.x;
    __shared__ float buf[8192];
    __shared__ float inv[32];

    for (int f = tid; f < 8192; f += 256) {
        int col;
        if (f < 2048) {
            col = (f >> 7) * 768 + (f & 127);
        } else if (f < 4096) {
            int ff = f - 2048;
            col = (ff >> 7) * 768 + 128 + (ff & 127);
        } else {
            int ff = f - 4096;
            int hv = ff >> 7;
            col = (hv >> 1) * 768 + 256 + (hv & 1) * 128 + (ff & 127);
        }
        float4 w4 = *(const float4*)(conv_w + (size_t)f * 4);
        const float* pc = proj + col;
        float s;
        if (l >= 3) {
            s = w4.x * pc[(size_t)(l - 3) * NPROJ]
              + w4.y * pc[(size_t)(l - 2) * NPROJ]
              + w4.z * pc[(size_t)(l - 1) * NPROJ]
              + w4.w * pc[(size_t)l       * NPROJ];
        } else {
            s = w4.w * pc[(size_t)l * NPROJ];
            if (l >= 1) s += w4.z * pc[(size_t)(l - 1) * NPROJ];
            if (l >= 2) s += w4.y * pc[(size_t)(l - 2) * NPROJ];
        }
        s = s / (1.f + __expf(-s));
        buf[f] = s;
    }
    __syncthreads();
    {
        int grp = tid >> 3, sub = tid & 7;
        int base = (grp < 16) ? grp * 128 : 2048 + (grp - 16) * 128;
        float ss = 0.f;
#pragma unroll
        for (int i = 0; i < 16; i++) {
            float x = buf[base + sub * 16 + i];
            ss += x * x;
        }
        ss += __shfl_xor_sync(0xffffffffu, ss, 4);
        ss += __shfl_xor_sync(0xffffffffu, ss, 2);
        ss += __shfl_xor_sync(0xffffffffu, ss, 1);
        if (sub == 0) inv[grp] = rsqrtf(ss + 1e-6f);
    }
    __syncthreads();
    const float qscale = 0.08838834764831845f;
    for (int f = tid; f < 2048; f += 256) {
        qo[(size_t)l * 2048 + f] = buf[f]        * inv[f >> 7] * qscale;
        ko[(size_t)l * 2048 + f] = buf[2048 + f] * inv[16 + (f >> 7)];
    }
    for (int f = tid; f < 4096; f += 256)
        vo[(size_t)l * 4096 + f] = buf[4096 + f];
    if (tid < 32) {
        const float* prow = proj + (size_t)l * NPROJ;
        int hv = tid, hk = hv >> 1, gg = hv & 1;
        float bb = prow[QKVZ_N + hk * 4 + gg];
        float aa = prow[QKVZ_N + hk * 4 + 2 + gg];
        bo[(size_t)l * 32 + hv] = 1.f / (1.f + __expf(-bb));
        float x = aa + dt_bias[hv];
        float sp = (x > 20.f) ? x : log1pf(__expf(x));
        go[(size_t)l * 32 + hv] = -__expf(A_log[hv]) * sp;   // raw g
    }
}

// ---------------- WY precompute (f32x2): one CTA per (hv, chunk) ---------------
#define WY_SMEMF 14688
__global__ __launch_bounds__(256) void wy_kernel(
    const float* __restrict__ k, const float* __restrict__ q,
    const float* __restrict__ v, const float* __restrict__ g,
    const float* __restrict__ beta,
    float* __restrict__ ug, float* __restrict__ wkg, float* __restrict__ rkg,
    float* __restrict__ bqg, float* __restrict__ pg)
{
    extern __shared__ float s[];
    float* Ks  = s;             // [32][132]
    float* Qs  = s + 4224;      // [32][132]
    float* Vs  = s + 8448;      // [32][128]
    uint64_t* kk2 = (uint64_t*)(s + 12544);  // [32][32] packed (-m,-m)
    float* cum = s + 14592;     // [32]
    float* bet = s + 14624;     // [32]
    float* ps  = s + 14656;     // [32]

    const int hv = blockIdx.x >> 7;
    const int ch = blockIdx.x & 127;
    const int hk = hv >> 1;
    const int tid = threadIdx.x;
    const int t0 = ch * CHK;

#pragma unroll
    for (int jj = 0; jj < 4; jj++) {
        int f = tid + jj * 256;
        int t = f >> 5, d4 = f & 31;
        cpa16(smem_u32(Ks + t * 132 + d4 * 4),
              k + (size_t)(t0 + t) * KEY_DIM + hk * DKC + d4 * 4);
        cpa16(smem_u32(Qs + t * 132 + d4 * 4),
              q + (size_t)(t0 + t) * KEY_DIM + hk * DKC + d4 * 4);
        cpa16(smem_u32(Vs + t * 128 + d4 * 4),
              v + (size_t)(t0 + t) * VAL_DIM + hv * DVC + d4 * 4);
    }
    cpa_commit();
    if (tid < 32) bet[tid] = beta[(size_t)(t0 + tid) * NHV + hv];
    cpa_wait0();
    __syncthreads();
    if (tid == 0) {
        float a = 0.f;
        for (int i = 0; i < CHK; i++) {
            a += g[(size_t)(t0 + i) * NHV + hv];
            cum[i] = a;
        }
    }
    __syncthreads();
    if (tid < 32) ps[tid] = __expf(cum[tid]);

    // grams (packed f32x2), results kept in registers
    float akr[4], aqr[4];
#pragma unroll
    for (int i = 0; i < 4; i++) {
        int p = tid * 4 + i;
        int t = p >> 5, j = p & 31;
        const ulonglong2* kjp = (const ulonglong2*)(Ks + j * 132);
        const ulonglong2* ktp = (const ulonglong2*)(Ks + t * 132);
        const ulonglong2* qtp = (const ulonglong2*)(Qs + t * 132);
        uint64_t ak0 = 0ull, ak1 = 0ull, aq0 = 0ull, aq1 = 0ull;
#pragma unroll
        for (int d = 0; d < 32; d++) {
            ulonglong2 kj = kjp[d];
            ulonglong2 kt = ktp[d];
            ulonglong2 qt = qtp[d];
            ak0 = fma2(kt.x, kj.x, ak0);
            ak1 = fma2(kt.y, kj.y, ak1);
            aq0 = fma2(qt.x, kj.x, aq0);
            aq1 = fma2(qt.y, kj.y, aq1);
        }
        float2 fa = unpack2(add2(ak0, ak1));
        float2 fq = unpack2(add2(aq0, aq1));
        akr[i] = fa.x + fa.y;
        aqr[i] = fq.x + fq.y;
    }

    const size_t bbase = ((size_t)hv * NCHK + ch) * CHK * CHK;
    const size_t dbase = ((size_t)hv * NCHK + ch) * CHK * DKC;
#pragma unroll
    for (int i = 0; i < 4; i++) {
        int p = tid * 4 + i;
        int t = p >> 5, j = p & 31;
        bqg[bbase + p] = (j <= t) ? __expf(cum[t] - cum[j]) * aqr[i] : 0.f;
        float m = (j < t) ? bet[t] * __expf(cum[t] - cum[j]) * akr[i] : 0.f;
        kk2[p] = pack2(-m, -m);
    }
#pragma unroll
    for (int i = 0; i < 16; i++) {
        int f = tid + i * 256;
        int t = f >> 7, d = f & 127;
        rkg[dbase + f] = __expf(cum[31] - cum[t]) * Ks[t * 132 + d];
    }
    if (tid < 32) pg[((size_t)hv * NCHK + ch) * CHK + tid] = ps[tid];
    __syncthreads();

    // forward substitution, TWO columns per thread (packed f32x2)
    if (tid < 128) {
        const int half = tid >> 6;          // 0 = v-cols, 1 = k-cols
        const int c = (tid & 63) * 2;
        uint64_t x[32];
        if (half == 0) {
#pragma unroll
            for (int t = 0; t < 32; t++) {
                uint64_t v2 = *(const uint64_t*)(Vs + t * 128 + c);
                x[t] = mul2(v2, pack2(bet[t], bet[t]));
            }
        } else {
#pragma unroll
            for (int t = 0; t < 32; t++) {
                uint64_t k2 = *(const uint64_t*)(Ks + t * 132 + c);
                float sc2 = bet[t] * ps[t];
                x[t] = mul2(k2, pack2(sc2, sc2));
            }
        }
#pragma unroll
        for (int t = 1; t < 32; t++)
#pragma unroll
            for (int j = 0; j < t; j++)
                x[t] = fma2(kk2[t * 32 + j], x[j], x[t]);
        if (half == 0) {
#pragma unroll
            for (int t = 0; t < 32; t++)
                *(uint64_t*)(ug + dbase + t * 128 + c) = x[t];
        } else {
#pragma unroll
            for (int t = 0; t < 32; t++)
                *(uint64_t*)(wkg + dbase + t * 128 + c) = x[t];
        }
    }
}

// ---------------- chunked serial scan (f32x2) ----------------------------------
#define CS_STG 14400
#define CS_SMEMF (2 * CS_STG + 8192 + 1024)
__device__ __forceinline__ void cs_load(
    float* sbuf, const float* q, const float* wkg, const float* rkg,
    const float* ug, const float* bqg, const float* pg,
    int hv, int hk, int dvb, int ch, int tid)
{
    const size_t dbase = ((size_t)hv * NCHK + ch) * CHK * DKC;
    const size_t bbase = ((size_t)hv * NCHK + ch) * CHK * CHK;
#pragma unroll
    for (int j = 0; j < 4; j++) {
        int f = tid + j * 256;
        cpa16(smem_u32(sbuf + f * 4), wkg + dbase + f * 4);
        cpa16(smem_u32(sbuf + 8192 + f * 4), rkg + dbase + f * 4);
        int t = f >> 5, d4 = f & 31;
        cpa16(smem_u32(sbuf + 4096 + f * 4),
              q + (size_t)(ch * CHK + t) * KEY_DIM + hk * DKC + d4 * 4);
    }
    {
        int t = tid >> 3, c4 = tid & 7;
        cpa16(smem_u32(sbuf + 12288 + t * 32 + c4 * 4),
              ug + dbase + t * 128 + dvb * 32 + c4 * 4);
    }
    cpa16(smem_u32(sbuf + 13312 + tid * 4), bqg + bbase + tid * 4);
    if (tid < 8)
        cpa16(smem_u32(sbuf + 14336 + tid * 4),
              pg + ((size_t)hv * NCHK + ch) * CHK + tid * 4);
}

__global__ __launch_bounds__(256) void chunkscan_kernel(
    const float* __restrict__ q, const float* __restrict__ ug,
    const float* __restrict__ wkg, const float* __restrict__ rkg,
    const float* __restrict__ bqg, const float* __restrict__ pg,
    float* __restrict__ core)
{
    extern __shared__ float s[];
    float* part = s + 2 * CS_STG;        // [8][32][32]
    float* dlt  = part + 8192;           // [32][32]
    const int hv = blockIdx.x >> 2;
    const int dvb = blockIdx.x & 3;
    const int hk = hv >> 1;
    const int tid = threadIdx.x;
    const int dkq = tid >> 5;
    const int dv = tid & 31;

    uint64_t S2[8];                      // packed S pairs: S2[p] = dims (2p, 2p+1)
#pragma unroll
    for (int i = 0; i < 8; i++) S2[i] = 0ull;

    cs_load(s, q, wkg, rkg, ug, bqg, pg, hv, hk, dvb, 0, tid);
    cpa_commit();

    for (int ch = 0; ch < NCHK; ch++) {
        if (ch + 1 < NCHK) {
            cs_load(s + ((ch + 1) & 1) * CS_STG, q, wkg, rkg, ug, bqg, pg,
                    hv, hk, dvb, ch + 1, tid);
            cpa_commit();
            cpa_wait1();
        } else {
            cpa_wait0();
        }
        __syncthreads();
        float* sb = s + (ch & 1) * CS_STG;

        // a) part = Wk . S
#pragma unroll
        for (int t = 0; t < 32; t++) {
            const ulonglong2* wr = (const ulonglong2*)(sb + t * 128 + dkq * 16);
            uint64_t a0 = 0ull, a1 = 0ull;
#pragma unroll
            for (int i = 0; i < 4; i++) {
                ulonglong2 w = wr[i];
                a0 = fma2(w.x, S2[2 * i], a0);
                a1 = fma2(w.y, S2[2 * i + 1], a1);
            }
            float2 r = unpack2(add2(a0, a1));
            part[dkq * 1024 + t * 32 + dv] = r.x + r.y;
        }
        __syncthreads();

        // b) delta = u - sum(part)
        {
            int t = tid >> 3, d0 = (tid & 7) * 4;
            uint64_t s0 = 0ull, s1 = 0ull;
#pragma unroll
            for (int gg = 0; gg < 8; gg++) {
                ulonglong2 p4 = *(const ulonglong2*)(part + gg * 1024 + t * 32 + d0);
                s0 = add2(s0, p4.x);
                s1 = add2(s1, p4.y);
            }
            float2 f0 = unpack2(s0), f1 = unpack2(s1);
            float4 u4 = *(const float4*)(sb + 12288 + t * 32 + d0);
            float4 d4 = make_float4(u4.x - f0.x, u4.y - f0.y,
                                    u4.z - f1.x, u4.w - f1.y);
            *(float4*)(dlt + t * 32 + d0) = d4;
        }
        __syncthreads();

        // c) part = Q . S
#pragma unroll
        for (int t = 0; t < 32; t++) {
            const ulonglong2* qr = (const ulonglong2*)(sb + 4096 + t * 128 + dkq * 16);
            uint64_t a0 = 0ull, a1 = 0ull;
#pragma unroll
            for (int i = 0; i < 4; i++) {
                ulonglong2 w = qr[i];
                a0 = fma2(w.x, S2[2 * i], a0);
                a1 = fma2(w.y, S2[2 * i + 1], a1);
            }
            float2 r = unpack2(add2(a0, a1));
            part[dkq * 1024 + t * 32 + dv] = r.x + r.y;
        }
        __syncthreads();

        // d) o = P_t*(QS0) + Bq.delta  -> core
        {
            int t = tid >> 3, d0 = (tid & 7) * 4;
            uint64_t s0 = 0ull, s1 = 0ull;
#pragma unroll
            for (int gg = 0; gg < 8; gg++) {
                ulonglong2 p4 = *(const ulonglong2*)(part + gg * 1024 + t * 32 + d0);
                s0 = add2(s0, p4.x);
                s1 = add2(s1, p4.y);
            }
            float pt = sb[14336 + t];
            uint64_t pt2 = pack2(pt, pt);
            uint64_t o0 = mul2(s0, pt2), o1 = mul2(s1, pt2);
            const float* bq = sb + 13312 + t * 32;
#pragma unroll
            for (int j = 0; j < 32; j++) {
                uint64_t bb = pack2(bq[j], bq[j]);
                ulonglong2 dj = *(const ulonglong2*)(dlt + j * 32 + d0);
                o0 = fma2(bb, dj.x, o0);
                o1 = fma2(bb, dj.y, o1);
            }
            float2 a = unpack2(o0), b2 = unpack2(o1);
            *(float4*)&core[(size_t)(ch * CHK + t) * VAL_DIM
                            + hv * DVC + dvb * 32 + d0] =
                make_float4(a.x, a.y, b2.x, b2.y);
        }

        // e) S = P31*S + rk^T . delta
        {
            float ptot = sb[14336 + 31];
            uint64_t pt2 = pack2(ptot, ptot);
#pragma unroll
            for (int i = 0; i < 8; i++) S2[i] = mul2(S2[i], pt2);
#pragma unroll
            for (int t = 0; t < 32; t++) {
                float d = dlt[t * 32 + dv];
                uint64_t dd = pack2(d, d);
                const ulonglong2* rr = (const ulonglong2*)(sb + 8192 + t * 128 + dkq * 16);
#pragma unroll
                for (int i = 0; i < 4; i++) {
                    ulonglong2 r = rr[i];
                    S2[2 * i]     = fma2(r.x, dd, S2[2 * i]);
                    S2[2 * i + 1] = fma2(r.y, dd, S2[2 * i + 1]);
                }
            }
        }
        __syncthreads();
    }
}

// ---------------- RMS-ish norm + silu(z) gate -> hi/lo bf16 --------------------
__global__ __launch_bounds__(128) void normgate_kernel(
    const float* __restrict__ core, const float* __restrict__ proj,
    const float* __restrict__ norm_w,
    __nv_bfloat16* __restrict__ ghi, __nv_bfloat16* __restrict__ glo)
{
    const int bx = blockIdx.x;
    const int l = bx >> 5;
    const int hv = bx & 31;
    const int d = threadIdx.x;
    float c = core[(size_t)bx * 128 + d];
    float ss = c * c;
#pragma unroll
    for (int o = 16; o > 0; o >>= 1)
        ss += __shfl_xor_sync(0xffffffffu, ss, o);
    __shared__ float r4[4];
    if ((d & 31) == 0) r4[d >> 5] = ss;
    __syncthreads();
    float var = (r4[0] + r4[1] + r4[2] + r4[3]) * (1.f / 128.f);
    int hk = hv >> 1, gg = hv & 1;
    float z = proj[(size_t)l * NPROJ + hk * 768 + 512 + gg * 128 + d];
    float sz = z / (1.f + __expf(-z));
    float val = c * rsqrtf(var + 1e-6f) * norm_w[d] * sz;
    __nv_bfloat16 h = __float2bfloat16(val);
    size_t idx = (size_t)bx * 128 + d;
    ghi[idx] = h;
    glo[idx] = __float2bfloat16(val - __bfloat162float(h));
}

// ---------------- launch -------------------------------------------------------
extern "C" void kernel_launch(void* const* d_in, const int* in_sizes, int n_in,
                              void* d_out, int out_size)
{
    const float* hidden     = (const float*)d_in[0];
    const float* in_proj_w  = (const float*)d_in[1];
    const float* conv_w     = (const float*)d_in[2];
    const float* A_log      = (const float*)d_in[3];
    const float* dt_bias    = (const float*)d_in[4];
    const float* norm_w     = (const float*)d_in[5];
    const float* out_proj_w = (const float*)d_in[6];
    float* out = (float*)d_out;

    float *p_proj, *p_q, *p_k, *p_v, *p_g, *p_b, *p_core;
    float *p_u, *p_wk, *p_rk, *p_bq, *p_p;
    __nv_bfloat16 *p_hh, *p_hl, *p_w1h, *p_w1l, *p_gh, *p_gl, *p_w2h, *p_w2l;
    cudaGetSymbolAddress((void**)&p_proj, g_proj);
    cudaGetSymbolAddress((void**)&p_q,    g_q);
    cudaGetSymbolAddress((void**)&p_k,    g_k);
    cudaGetSymbolAddress((void**)&p_v,    g_v);
    cudaGetSymbolAddress((void**)&p_g,    g_gdec);
    cudaGetSymbolAddress((void**)&p_b,    g_beta);
    cudaGetSymbolAddress((void**)&p_core, g_core);
    cudaGetSymbolAddress((void**)&p_u,    g_u);
    cudaGetSymbolAddress((void**)&p_wk,   g_Wk);
    cudaGetSymbolAddress((void**)&p_rk,   g_rk);
    cudaGetSymbolAddress((void**)&p_bq,   g_Bq);
    cudaGetSymbolAddress((void**)&p_p,    g_P);
    cudaGetSymbolAddress((void**)&p_hh,   g_hid_hi);
    cudaGetSymbolAddress((void**)&p_hl,   g_hid_lo);
    cudaGetSymbolAddress((void**)&p_w1h,  g_w1_hi);
    cudaGetSymbolAddress((void**)&p_w1l,  g_w1_lo);
    cudaGetSymbolAddress((void**)&p_gh,   g_gat_hi);
    cudaGetSymbolAddress((void**)&p_gl,   g_gat_lo);
    cudaGetSymbolAddress((void**)&p_w2h,  g_w2_hi);
    cudaGetSymbolAddress((void**)&p_w2l,  g_w2_lo);

    cudaFuncSetAttribute(gemm_b3_kernel,
                         cudaFuncAttributeMaxDynamicSharedMemorySize, GEMM_SMEM);
    cudaFuncSetAttribute(wy_kernel,
                         cudaFuncAttributeMaxDynamicSharedMemorySize, WY_SMEMF * 4);
    cudaFuncSetAttribute(chunkscan_kernel,
                         cudaFuncAttributeMaxDynamicSharedMemorySize, CS_SMEMF * 4);

    {
        size_t n = (size_t)LSEQ * HDIM;
        conv_hl_kernel<<<(unsigned)((n + 255) / 256), 256>>>(hidden, p_hh, p_hl, n);
    }
    convT_kernel<<<dim3(NPAD1 / 32, HDIM / 32), 256>>>(in_proj_w, p_w1h, p_w1l,
                                                       HDIM, NPROJ);
    convT_kernel<<<dim3(HDIM / 32, VAL_DIM / 32), 256>>>(out_proj_w, p_w2h, p_w2l,
                                                         VAL_DIM, HDIM);

    gemm_b3_kernel<<<dim3(NPAD1 / 128, LSEQ / 128), 256, GEMM_SMEM>>>(
        p_hh, p_hl, p_w1h, p_w1l, p_proj, LSEQ, NPROJ, HDIM);

    prep_kernel<<<LSEQ, 256>>>(p_proj, conv_w, A_log, dt_bias,
                               p_q, p_k, p_v, p_g, p_b);

    wy_kernel<<<NHV * NCHK, 256, WY_SMEMF * 4>>>(p_k, p_q, p_v, p_g, p_b,
                                                 p_u, p_wk, p_rk, p_bq, p_p);

    chunkscan_kernel<<<NHV * 4, 256, CS_SMEMF * 4>>>(p_q, p_u, p_wk, p_rk,
                                                     p_bq, p_p, p_core);

    normgate_kernel<<<LSEQ * NHV, 128>>>(p_core, p_proj, norm_w, p_gh, p_gl);

    gemm_b3_kernel<<<dim3(HDIM / 128, LSEQ / 128), 256, GEMM_SMEM>>>(
        p_gh, p_gl, p_w2h, p_w2l, out, LSEQ, HDIM, VAL_DIM);
}

// round 14
// speedup vs baseline: 1.0936x; 1.0936x over previous
#include <cuda_runtime.h>
#include <cuda_bf16.h>
#include <cstdint>

#define LSEQ   4096
#define HDIM   2048
#define NPROJ  12352
#define QKVZ_N 12288
#define KEY_DIM 2048
#define VAL_DIM 4096
#define NHV    32
#define DKC    128
#define DVC    128
#define NPAD1  12416
#define CHK    32
#define NCHK   128

__device__ float g_proj [(size_t)LSEQ * NPROJ];
__device__ float g_q    [(size_t)LSEQ * KEY_DIM];
__device__ float g_k    [(size_t)LSEQ * KEY_DIM];
__device__ float g_v    [(size_t)LSEQ * VAL_DIM];
__device__ float g_gdec [(size_t)LSEQ * NHV];   // raw g
__device__ float g_beta [(size_t)LSEQ * NHV];
__device__ float g_core [(size_t)LSEQ * VAL_DIM];

__device__ float g_u  [(size_t)NHV * NCHK * CHK * DKC];
__device__ float g_Wk [(size_t)NHV * NCHK * CHK * DKC];
__device__ float g_Bq [(size_t)NHV * NCHK * CHK * CHK];
__device__ float g_P  [(size_t)NHV * NCHK * CHK];
__device__ float g_R  [(size_t)NHV * NCHK * CHK];   // exp(cum31 - cum_t)

__device__ __nv_bfloat16 g_hid_hi[(size_t)LSEQ * HDIM];
__device__ __nv_bfloat16 g_hid_lo[(size_t)LSEQ * HDIM];
__device__ __nv_bfloat16 g_w1_hi [(size_t)NPAD1 * HDIM];
__device__ __nv_bfloat16 g_w1_lo [(size_t)NPAD1 * HDIM];
__device__ __nv_bfloat16 g_gat_hi[(size_t)LSEQ * VAL_DIM];
__device__ __nv_bfloat16 g_gat_lo[(size_t)LSEQ * VAL_DIM];
__device__ __nv_bfloat16 g_w2_hi [(size_t)HDIM * VAL_DIM];
__device__ __nv_bfloat16 g_w2_lo [(size_t)HDIM * VAL_DIM];

__device__ __forceinline__ uint32_t smem_u32(const void* p) {
    uint32_t a;
    asm("{ .reg .u64 t; cvta.to.shared.u64 t, %1; cvt.u32.u64 %0, t; }"
        : "=r"(a) : "l"(p));
    return a;
}
#define SW64(x) ((x) ^ (((x) >> 3) & 0x30))
__device__ __forceinline__ void cpa16(uint32_t s, const void* g) {
    asm volatile("cp.async.cg.shared.global [%0], [%1], 16;" :: "r"(s), "l"(g));
}
__device__ __forceinline__ void cpa_commit() {
    asm volatile("cp.async.commit_group;" ::: "memory");
}
__device__ __forceinline__ void cpa_wait1() {
    asm volatile("cp.async.wait_group 1;" ::: "memory");
}
__device__ __forceinline__ void cpa_wait0() {
    asm volatile("cp.async.wait_group 0;" ::: "memory");
}
__device__ __forceinline__ void ldsm4(uint32_t& r0, uint32_t& r1, uint32_t& r2,
                                      uint32_t& r3, uint32_t a) {
    asm volatile("ldmatrix.sync.aligned.m8n8.x4.shared.b16 {%0,%1,%2,%3}, [%4];"
                 : "=r"(r0), "=r"(r1), "=r"(r2), "=r"(r3) : "r"(a));
}
__device__ __forceinline__ void mma16816(float* c, const uint32_t* a,
                                         const uint32_t* b) {
    asm volatile(
        "mma.sync.aligned.m16n8k16.row.col.f32.bf16.bf16.f32 "
        "{%0,%1,%2,%3}, {%4,%5,%6,%7}, {%8,%9}, {%0,%1,%2,%3};"
        : "+f"(c[0]), "+f"(c[1]), "+f"(c[2]), "+f"(c[3])
        : "r"(a[0]), "r"(a[1]), "r"(a[2]), "r"(a[3]), "r"(b[0]), "r"(b[1]));
}

// ---- packed f32x2 ----
__device__ __forceinline__ uint64_t fma2(uint64_t a, uint64_t b, uint64_t c) {
    uint64_t d;
    asm("fma.rn.f32x2 %0, %1, %2, %3;" : "=l"(d) : "l"(a), "l"(b), "l"(c));
    return d;
}
__device__ __forceinline__ uint64_t add2(uint64_t a, uint64_t b) {
    uint64_t d;
    asm("add.rn.f32x2 %0, %1, %2;" : "=l"(d) : "l"(a), "l"(b));
    return d;
}
__device__ __forceinline__ uint64_t mul2(uint64_t a, uint64_t b) {
    uint64_t d;
    asm("mul.rn.f32x2 %0, %1, %2;" : "=l"(d) : "l"(a), "l"(b));
    return d;
}
__device__ __forceinline__ uint64_t pack2(float x, float y) {
    uint64_t d;
    asm("mov.b64 %0, {%1, %2};" : "=l"(d) : "f"(x), "f"(y));
    return d;
}
__device__ __forceinline__ float2 unpack2(uint64_t v) {
    float x, y;
    asm("mov.b64 {%0, %1}, %2;" : "=f"(x), "=f"(y) : "l"(v));
    return make_float2(x, y);
}

// ---------------- bf16x3 mma.sync GEMM (unchanged) -----------------------------
#define GSTAGE 32768
#define NSTAGE 3
#define GEMM_SMEM (NSTAGE * GSTAGE)

__global__ __launch_bounds__(256, 2) void gemm_b3_kernel(
    const __nv_bfloat16* __restrict__ Ahi, const __nv_bfloat16* __restrict__ Alo,
    const __nv_bfloat16* __restrict__ Bhi, const __nv_bfloat16* __restrict__ Blo,
    float* __restrict__ C, int M, int N, int K)
{
    extern __shared__ char smem[];
    const uint32_t sb = smem_u32(smem);
    const int tid = threadIdx.x;
    const int wid = tid >> 5;
    const int lane = tid & 31;
    const int wm = wid >> 1;
    const int wn = wid & 1;
    const int bm = blockIdx.y * 128;
    const int bn = blockIdx.x * 128;
    const int rowh = tid >> 2;
    const int kc = tid & 3;
    const __nv_bfloat16* gp[4];
    gp[0] = Ahi + (size_t)bm * K;
    gp[1] = Alo + (size_t)bm * K;
    gp[2] = Bhi + (size_t)bn * K;
    gp[3] = Blo + (size_t)bn * K;

    float acc[2][8][4];
#pragma unroll
    for (int i = 0; i < 2; i++)
#pragma unroll
        for (int j = 0; j < 8; j++)
#pragma unroll
            for (int x = 0; x < 4; x++) acc[i][j][x] = 0.f;

    const int nk = K >> 5;
    uint32_t aoff[2][2], boff[4][2];
#pragma unroll
    for (int t = 0; t < 2; t++)
#pragma unroll
        for (int ks = 0; ks < 2; ks++)
            aoff[t][ks] = SW64(((wm * 32 + t * 16 + (lane & 15)) << 6)
                               + ks * 32 + ((lane >> 4) << 4));
#pragma unroll
    for (int p = 0; p < 4; p++)
#pragma unroll
        for (int ks = 0; ks < 2; ks++)
            boff[p][ks] = SW64(((wn * 64 + p * 16 + ((lane >> 4) << 3) + (lane & 7)) << 6)
                               + ks * 32 + (((lane >> 3) & 1) << 4)) + 16384;

#pragma unroll
    for (int s = 0; s < 2; s++) {
        const size_t k0 = (size_t)s << 5;
        const uint32_t stb = sb + s * GSTAGE;
#pragma unroll
        for (int j = 0; j < 8; j++) {
            const int tile = j >> 1;
            const int row = ((j & 1) << 6) + rowh;
            cpa16(stb + (tile << 13) + SW64((row << 6) + kc * 16),
                  gp[tile] + (size_t)row * K + k0 + kc * 8);
        }
        cpa_commit();
    }

    int sc = 0, sp = 2;
    for (int kt = 0; kt < nk; ++kt) {
        if (kt < nk - 1) cpa_wait1();
        else             cpa_wait0();
        __syncthreads();
        if (kt + 2 < nk) {
            const size_t k0 = (size_t)(kt + 2) << 5;
            const uint32_t stb = sb + sp * GSTAGE;
#pragma unroll
            for (int j = 0; j < 8; j++) {
                const int tile = j >> 1;
                const int row = ((j & 1) << 6) + rowh;
                cpa16(stb + (tile << 13) + SW64((row << 6) + kc * 16),
                      gp[tile] + (size_t)row * K + k0 + kc * 8);
            }
            cpa_commit();
        }
        const uint32_t base = sb + sc * GSTAGE;
        if (++sc == NSTAGE) sc = 0;
        if (++sp == NSTAGE) sp = 0;
#pragma unroll
        for (int ks = 0; ks < 2; ks++) {
            uint32_t ah[2][4], al[2][4], bh[8][2];
#pragma unroll
            for (int t = 0; t < 2; t++) {
                ldsm4(ah[t][0], ah[t][1], ah[t][2], ah[t][3], base + aoff[t][ks]);
                ldsm4(al[t][0], al[t][1], al[t][2], al[t][3], base + 8192 + aoff[t][ks]);
            }
#pragma unroll
            for (int p = 0; p < 4; p++)
                ldsm4(bh[2 * p][0], bh[2 * p][1], bh[2 * p + 1][0], bh[2 * p + 1][1],
                      base + boff[p][ks]);
#pragma unroll
            for (int i = 0; i < 2; i++)
#pragma unroll
                for (int j = 0; j < 8; j++)
                    mma16816(acc[i][j], ah[i], bh[j]);
#pragma unroll
            for (int i = 0; i < 2; i++)
#pragma unroll
                for (int j = 0; j < 8; j++)
                    mma16816(acc[i][j], al[i], bh[j]);
#pragma unroll
            for (int p = 0; p < 4; p++) {
                uint32_t bl0[2], bl1[2];
                ldsm4(bl0[0], bl0[1], bl1[0], bl1[1], base + 8192 + boff[p][ks]);
                mma16816(acc[0][2 * p],     ah[0], bl0);
                mma16816(acc[1][2 * p],     ah[1], bl0);
                mma16816(acc[0][2 * p + 1], ah[0], bl1);
                mma16816(acc[1][2 * p + 1], ah[1], bl1);
            }
        }
    }
#pragma unroll
    for (int i = 0; i < 2; i++) {
        const int r0 = bm + wm * 32 + i * 16 + (lane >> 2);
#pragma unroll
        for (int j = 0; j < 8; j++) {
            const int col = bn + wn * 64 + j * 8 + (lane & 3) * 2;
            if (col < N) {
                *(float2*)&C[(size_t)r0 * N + col] =
                    make_float2(acc[i][j][0], acc[i][j][1]);
                *(float2*)&C[(size_t)(r0 + 8) * N + col] =
                    make_float2(acc[i][j][2], acc[i][j][3]);
            }
        }
    }
}

// ---------------- conversions --------------------------------------------------
__global__ __launch_bounds__(256) void conv_hl_kernel(
    const float* __restrict__ X, __nv_bfloat16* __restrict__ hi,
    __nv_bfloat16* __restrict__ lo, size_t n)
{
    size_t i = (size_t)blockIdx.x * 256 + threadIdx.x;
    if (i < n) {
        float x = X[i];
        __nv_bfloat16 h = __float2bfloat16(x);
        hi[i] = h;
        lo[i] = __float2bfloat16(x - __bfloat162float(h));
    }
}

__global__ __launch_bounds__(256) void convT_kernel(
    const float* __restrict__ W, __nv_bfloat16* __restrict__ hi,
    __nv_bfloat16* __restrict__ lo, int K, int N)
{
    __shared__ float t[32][33];
    const int nb = blockIdx.x * 32;
    const int kb = blockIdx.y * 32;
    const int tx = threadIdx.x & 31;
    const int ty = threadIdx.x >> 5;
#pragma unroll
    for (int p = 0; p < 4; p++) {
        int r = ty + p * 8;
        int n = nb + tx;
        t[r][tx] = (n < N) ? W[(size_t)(kb + r) * N + n] : 0.f;
    }
    __syncthreads();
#pragma unroll
    for (int p = 0; p < 4; p++) {
        int r = ty + p * 8;
        float x = t[tx][r];
        __nv_bfloat16 h = __float2bfloat16(x);
        __nv_bfloat16 l = __float2bfloat16(x - __bfloat162float(h));
        size_t o = (size_t)(nb + r) * K + kb + tx;
        hi[o] = h;
        lo[o] = l;
    }
}

// ---------------- conv(K=4) + silu + l2norm + gating prep ----------------------
__global__ __launch_bounds__(256) void prep_kernel(
    const float* __restrict__ proj, const float* __restrict__ conv_w,
    const float* __restrict__ A_log, const float* __restrict__ dt_bias,
    float* __restrict__ qo, float* __restrict__ ko, float* __restrict__ vo,
    float* __restrict__ go, float* __restrict__ bo)
{
    const int l = blockIdx.x;
    const int tid = threadIdx.x;
    __shared__ float buf[8192];
    __shared__ float inv[32];

    for (int f = tid; f < 8192; f += 256) {
        int col;
        if (f < 2048) {
            col = (f >> 7) * 768 + (f & 127);
        } else if (f < 4096) {
            int ff = f - 2048;
            col = (ff >> 7) * 768 + 128 + (ff & 127);
        } else {
            int ff = f - 4096;
            int hv = ff >> 7;
            col = (hv >> 1) * 768 + 256 + (hv & 1) * 128 + (ff & 127);
        }
        float4 w4 = *(const float4*)(conv_w + (size_t)f * 4);
        const float* pc = proj + col;
        float s;
        if (l >= 3) {
            s = w4.x * pc[(size_t)(l - 3) * NPROJ]
              + w4.y * pc[(size_t)(l - 2) * NPROJ]
              + w4.z * pc[(size_t)(l - 1) * NPROJ]
              + w4.w * pc[(size_t)l       * NPROJ];
        } else {
            s = w4.w * pc[(size_t)l * NPROJ];
            if (l >= 1) s += w4.z * pc[(size_t)(l - 1) * NPROJ];
            if (l >= 2) s += w4.y * pc[(size_t)(l - 2) * NPROJ];
        }
        s = s / (1.f + __expf(-s));
        buf[f] = s;
    }
    __syncthreads();
    {
        int grp = tid >> 3, sub = tid & 7;
        int base = (grp < 16) ? grp * 128 : 2048 + (grp - 16) * 128;
        float ss = 0.f;
#pragma unroll
        for (int i = 0; i < 16; i++) {
            float x = buf[base + sub * 16 + i];
            ss += x * x;
        }
        ss += __shfl_xor_sync(0xffffffffu, ss, 4);
        ss += __shfl_xor_sync(0xffffffffu, ss, 2);
        ss += __shfl_xor_sync(0xffffffffu, ss, 1);
        if (sub == 0) inv[grp] = rsqrtf(ss + 1e-6f);
    }
    __syncthreads();
    const float qscale = 0.08838834764831845f;
    for (int f = tid; f < 2048; f += 256) {
        qo[(size_t)l * 2048 + f] = buf[f]        * inv[f >> 7] * qscale;
        ko[(size_t)l * 2048 + f] = buf[2048 + f] * inv[16 + (f >> 7)];
    }
    for (int f = tid; f < 4096; f += 256)
        vo[(size_t)l * 4096 + f] = buf[4096 + f];
    if (tid < 32) {
        const float* prow = proj + (size_t)l * NPROJ;
        int hv = tid, hk = hv >> 1, gg = hv & 1;
        float bb = prow[QKVZ_N + hk * 4 + gg];
        float aa = prow[QKVZ_N + hk * 4 + 2 + gg];
        bo[(size_t)l * 32 + hv] = 1.f / (1.f + __expf(-bb));
        float x = aa + dt_bias[hv];
        float sp = (x > 20.f) ? x : log1pf(__expf(x));
        go[(size_t)l * 32 + hv] = -__expf(A_log[hv]) * sp;   // raw g
    }
}

// ---------------- WY precompute (f32x2, conflict-free grams) -------------------
#define WY_SMEMF 14688
__global__ __launch_bounds__(256) void wy_kernel(
    const float* __restrict__ k, const float* __restrict__ q,
    const float* __restrict__ v, const float* __restrict__ g,
    const float* __restrict__ beta,
    float* __restrict__ ug, float* __restrict__ wkg,
    float* __restrict__ bqg, float* __restrict__ pg, float* __restrict__ rg)
{
    extern __shared__ float s[];
    float* Ks  = s;             // [32][132]
    float* Qs  = s + 4224;      // [32][132]
    float* Vs  = s + 8448;      // [32][128]
    uint64_t* kk2 = (uint64_t*)(s + 12544);  // [32][32] packed (-m,-m)
    float* cum = s + 14592;     // [32]
    float* bet = s + 14624;     // [32]
    float* ps  = s + 14656;     // [32]

    const int hv = blockIdx.x >> 7;
    const int ch = blockIdx.x & 127;
    const int hk = hv >> 1;
    const int tid = threadIdx.x;
    const int t0 = ch * CHK;

#pragma unroll
    for (int jj = 0; jj < 4; jj++) {
        int f = tid + jj * 256;
        int t = f >> 5, d4 = f & 31;
        cpa16(smem_u32(Ks + t * 132 + d4 * 4),
              k + (size_t)(t0 + t) * KEY_DIM + hk * DKC + d4 * 4);
        cpa16(smem_u32(Qs + t * 132 + d4 * 4),
              q + (size_t)(t0 + t) * KEY_DIM + hk * DKC + d4 * 4);
        cpa16(smem_u32(Vs + t * 128 + d4 * 4),
              v + (size_t)(t0 + t) * VAL_DIM + hv * DVC + d4 * 4);
    }
    cpa_commit();
    if (tid < 32) bet[tid] = beta[(size_t)(t0 + tid) * NHV + hv];
    cpa_wait0();
    __syncthreads();
    if (tid == 0) {
        float a = 0.f;
        for (int i = 0; i < CHK; i++) {
            a += g[(size_t)(t0 + i) * NHV + hv];
            cum[i] = a;
        }
    }
    __syncthreads();
    if (tid < 32) ps[tid] = __expf(cum[tid]);

    // grams: t = tid>>3, j = (tid&7) + 8i  (conflict-free: consecutive lanes ->
    // consecutive j rows, 528B apart -> distinct 16B banks)
    const int gt = tid >> 3;
    const int j0 = tid & 7;
    float akr[4], aqr[4];
    {
        const ulonglong2* ktp = (const ulonglong2*)(Ks + gt * 132);
        const ulonglong2* qtp = (const ulonglong2*)(Qs + gt * 132);
        const ulonglong2* kjp = (const ulonglong2*)(Ks + j0 * 132);
        uint64_t ak[4][2], aq[4][2];
#pragma unroll
        for (int i = 0; i < 4; i++) {
            ak[i][0] = ak[i][1] = 0ull;
            aq[i][0] = aq[i][1] = 0ull;
        }
#pragma unroll
        for (int d = 0; d < 32; d++) {
            ulonglong2 kt = ktp[d];
            ulonglong2 qt = qtp[d];
#pragma unroll
            for (int i = 0; i < 4; i++) {
                ulonglong2 kj = kjp[i * 8 * 33 + d];   // row j0+8i (132 fl = 33 u2)
                ak[i][0] = fma2(kt.x, kj.x, ak[i][0]);
                ak[i][1] = fma2(kt.y, kj.y, ak[i][1]);
                aq[i][0] = fma2(qt.x, kj.x, aq[i][0]);
                aq[i][1] = fma2(qt.y, kj.y, aq[i][1]);
            }
        }
#pragma unroll
        for (int i = 0; i < 4; i++) {
            float2 fa = unpack2(add2(ak[i][0], ak[i][1]));
            float2 fq = unpack2(add2(aq[i][0], aq[i][1]));
            akr[i] = fa.x + fa.y;
            aqr[i] = fq.x + fq.y;
        }
    }

    const size_t bbase = ((size_t)hv * NCHK + ch) * CHK * CHK;
    const size_t dbase = ((size_t)hv * NCHK + ch) * CHK * DKC;
#pragma unroll
    for (int i = 0; i < 4; i++) {
        int j = j0 + 8 * i;
        int p = gt * 32 + j;
        bqg[bbase + p] = (j <= gt) ? __expf(cum[gt] - cum[j]) * aqr[i] : 0.f;
        float m = (j < gt) ? bet[gt] * __expf(cum[gt] - cum[j]) * akr[i] : 0.f;
        kk2[p] = pack2(-m, -m);
    }
    if (tid < 32) {
        pg[((size_t)hv * NCHK + ch) * CHK + tid] = ps[tid];
        rg[((size_t)hv * NCHK + ch) * CHK + tid] = __expf(cum[31] - cum[tid]);
    }
    __syncthreads();

    // forward substitution, TWO columns per thread (packed f32x2)
    if (tid < 128) {
        const int half = tid >> 6;          // 0 = v-cols, 1 = k-cols
        const int c = (tid & 63) * 2;
        uint64_t x[32];
        if (half == 0) {
#pragma unroll
            for (int t = 0; t < 32; t++) {
                uint64_t v2 = *(const uint64_t*)(Vs + t * 128 + c);
                x[t] = mul2(v2, pack2(bet[t], bet[t]));
            }
        } else {
#pragma unroll
            for (int t = 0; t < 32; t++) {
                uint64_t k2 = *(const uint64_t*)(Ks + t * 132 + c);
                float sc2 = bet[t] * ps[t];
                x[t] = mul2(k2, pack2(sc2, sc2));
            }
        }
#pragma unroll
        for (int t = 1; t < 32; t++)
#pragma unroll
            for (int j = 0; j < t; j++)
                x[t] = fma2(kk2[t * 32 + j], x[j], x[t]);
        if (half == 0) {
#pragma unroll
            for (int t = 0; t < 32; t++)
                *(uint64_t*)(ug + dbase + t * 128 + c) = x[t];
        } else {
#pragma unroll
            for (int t = 0; t < 32; t++)
                *(uint64_t*)(wkg + dbase + t * 128 + c) = x[t];
        }
    }
}

// ---------------- chunked serial scan (f32x2, 3 syncs/chunk) -------------------
// Stage layout (floats): Wk[0,4096) Q[4096,8192) K[8192,12288) u[12288,13312)
// Bq[13312,14336) P[14336,14368) R[14368,14400). E uses raw K scaled by R_t
// folded into delta.
#define CS_STG 14400
#define CS_SMEMF (2 * CS_STG + 8192 + 8192 + 1024)
__device__ __forceinline__ void cs_load(
    float* sbuf, const float* q, const float* k, const float* wkg,
    const float* ug, const float* bqg, const float* pg, const float* rg,
    int hv, int hk, int dvb, int ch, int tid)
{
    const size_t dbase = ((size_t)hv * NCHK + ch) * CHK * DKC;
    const size_t bbase = ((size_t)hv * NCHK + ch) * CHK * CHK;
#pragma unroll
    for (int j = 0; j < 4; j++) {
        int f = tid + j * 256;
        cpa16(smem_u32(sbuf + f * 4), wkg + dbase + f * 4);
        int t = f >> 5, d4 = f & 31;
        cpa16(smem_u32(sbuf + 4096 + f * 4),
              q + (size_t)(ch * CHK + t) * KEY_DIM + hk * DKC + d4 * 4);
        cpa16(smem_u32(sbuf + 8192 + f * 4),
              k + (size_t)(ch * CHK + t) * KEY_DIM + hk * DKC + d4 * 4);
    }
    {
        int t = tid >> 3, c4 = tid & 7;
        cpa16(smem_u32(sbuf + 12288 + t * 32 + c4 * 4),
              ug + dbase + t * 128 + dvb * 32 + c4 * 4);
    }
    cpa16(smem_u32(sbuf + 13312 + tid * 4), bqg + bbase + tid * 4);
    if (tid < 8)
        cpa16(smem_u32(sbuf + 14336 + tid * 4),
              pg + ((size_t)hv * NCHK + ch) * CHK + tid * 4);
    else if (tid < 16)
        cpa16(smem_u32(sbuf + 14368 + (tid - 8) * 4),
              rg + ((size_t)hv * NCHK + ch) * CHK + (tid - 8) * 4);
}

__global__ __launch_bounds__(256) void chunkscan_kernel(
    const float* __restrict__ q, const float* __restrict__ k,
    const float* __restrict__ ug, const float* __restrict__ wkg,
    const float* __restrict__ bqg, const float* __restrict__ pg,
    const float* __restrict__ rg, float* __restrict__ core)
{
    extern __shared__ float s[];
    float* part  = s + 2 * CS_STG;       // [8][32][32] Wk.S partials
    float* part2 = part + 8192;          // [8][32][32] Q.S partials
    float* dlt   = part2 + 8192;         // [32][32]
    const int hv = blockIdx.x >> 2;
    const int dvb = blockIdx.x & 3;
    const int hk = hv >> 1;
    const int tid = threadIdx.x;
    const int dkq = tid >> 5;
    const int dv = tid & 31;

    uint64_t S2[8];
#pragma unroll
    for (int i = 0; i < 8; i++) S2[i] = 0ull;

    cs_load(s, q, k, wkg, ug, bqg, pg, rg, hv, hk, dvb, 0, tid);
    cpa_commit();

    for (int ch = 0; ch < NCHK; ch++) {
        if (ch + 1 < NCHK) cpa_wait1();
        else               cpa_wait0();
        __syncthreads();                           // sync0
        if (ch + 1 < NCHK) {
            cs_load(s + ((ch + 1) & 1) * CS_STG, q, k, wkg, ug, bqg, pg, rg,
                    hv, hk, dvb, ch + 1, tid);
            cpa_commit();
        }
        float* sb = s + (ch & 1) * CS_STG;

        // AC) part = Wk.S, part2 = Q.S
#pragma unroll
        for (int t = 0; t < 32; t++) {
            const ulonglong2* wr = (const ulonglong2*)(sb + t * 128 + dkq * 16);
            const ulonglong2* qr = (const ulonglong2*)(sb + 4096 + t * 128 + dkq * 16);
            uint64_t a0 = 0ull, a1 = 0ull, q0 = 0ull, q1 = 0ull;
#pragma unroll
            for (int i = 0; i < 4; i++) {
                ulonglong2 w = wr[i];
                ulonglong2 qq = qr[i];
                a0 = fma2(w.x, S2[2 * i], a0);
                a1 = fma2(w.y, S2[2 * i + 1], a1);
                q0 = fma2(qq.x, S2[2 * i], q0);
                q1 = fma2(qq.y, S2[2 * i + 1], q1);
            }
            float2 ra = unpack2(add2(a0, a1));
            float2 rq = unpack2(add2(q0, q1));
            part [dkq * 1024 + t * 32 + dv] = ra.x + ra.y;
            part2[dkq * 1024 + t * 32 + dv] = rq.x + rq.y;
        }
        __syncthreads();                           // sync1

        // B) delta = u - sum(part)
        {
            int t = tid >> 3, d0 = (tid & 7) * 4;
            uint64_t s0 = 0ull, s1 = 0ull;
#pragma unroll
            for (int gg = 0; gg < 8; gg++) {
                ulonglong2 p4 = *(const ulonglong2*)(part + gg * 1024 + t * 32 + d0);
                s0 = add2(s0, p4.x);
                s1 = add2(s1, p4.y);
            }
            float2 f0 = unpack2(s0), f1 = unpack2(s1);
            float4 u4 = *(const float4*)(sb + 12288 + t * 32 + d0);
            float4 d4 = make_float4(u4.x - f0.x, u4.y - f0.y,
                                    u4.z - f1.x, u4.w - f1.y);
            *(float4*)(dlt + t * 32 + d0) = d4;
        }
        __syncthreads();                           // sync2

        // E) S = P31*S + K^T . (R_t * delta)   (register-local after sync2)
        {
            float ptot = sb[14336 + 31];
            uint64_t pt2 = pack2(ptot, ptot);
#pragma unroll
            for (int i = 0; i < 8; i++) S2[i] = mul2(S2[i], pt2);
#pragma unroll
            for (int t = 0; t < 32; t++) {
                float d = dlt[t * 32 + dv] * sb[14368 + t];
                uint64_t dd = pack2(d, d);
                const ulonglong2* rr = (const ulonglong2*)(sb + 8192 + t * 128 + dkq * 16);
#pragma unroll
                for (int i = 0; i < 4; i++) {
                    ulonglong2 r = rr[i];
                    S2[2 * i]     = fma2(r.x, dd, S2[2 * i]);
                    S2[2 * i + 1] = fma2(r.y, dd, S2[2 * i + 1]);
                }
            }
        }

        // D) o = P_t*(Q.S0) + Bq.delta -> core
        {
            int t = tid >> 3, d0 = (tid & 7) * 4;
            uint64_t s0 = 0ull, s1 = 0ull;
#pragma unroll
            for (int gg = 0; gg < 8; gg++) {
                ulonglong2 p4 = *(const ulonglong2*)(part2 + gg * 1024 + t * 32 + d0);
                s0 = add2(s0, p4.x);
                s1 = add2(s1, p4.y);
            }
            float pt = sb[14336 + t];
            uint64_t pt2 = pack2(pt, pt);
            uint64_t o0 = mul2(s0, pt2), o1 = mul2(s1, pt2);
            const float* bq = sb + 13312 + t * 32;
#pragma unroll
            for (int j = 0; j < 32; j++) {
                uint64_t bb = pack2(bq[j], bq[j]);
                ulonglong2 dj = *(const ulonglong2*)(dlt + j * 32 + d0);
                o0 = fma2(bb, dj.x, o0);
                o1 = fma2(bb, dj.y, o1);
            }
            float2 a = unpack2(o0), b2 = unpack2(o1);
            *(float4*)&core[(size_t)(ch * CHK + t) * VAL_DIM
                            + hv * DVC + dvb * 32 + d0] =
                make_float4(a.x, a.y, b2.x, b2.y);
        }
        // no end-of-loop sync: loop-top sync0 provides ordering
    }
}

// ---------------- RMS-ish norm + silu(z) gate -> hi/lo bf16 --------------------
__global__ __launch_bounds__(128) void normgate_kernel(
    const float* __restrict__ core, const float* __restrict__ proj,
    const float* __restrict__ norm_w,
    __nv_bfloat16* __restrict__ ghi, __nv_bfloat16* __restrict__ glo)
{
    const int bx = blockIdx.x;
    const int l = bx >> 5;
    const int hv = bx & 31;
    const int d = threadIdx.x;
    float c = core[(size_t)bx * 128 + d];
    float ss = c * c;
#pragma unroll
    for (int o = 16; o > 0; o >>= 1)
        ss += __shfl_xor_sync(0xffffffffu, ss, o);
    __shared__ float r4[4];
    if ((d & 31) == 0) r4[d >> 5] = ss;
    __syncthreads();
    float var = (r4[0] + r4[1] + r4[2] + r4[3]) * (1.f / 128.f);
    int hk = hv >> 1, gg = hv & 1;
    float z = proj[(size_t)l * NPROJ + hk * 768 + 512 + gg * 128 + d];
    float sz = z / (1.f + __expf(-z));
    float val = c * rsqrtf(var + 1e-6f) * norm_w[d] * sz;
    __nv_bfloat16 h = __float2bfloat16(val);
    size_t idx = (size_t)bx * 128 + d;
    ghi[idx] = h;
    glo[idx] = __float2bfloat16(val - __bfloat162float(h));
}

// ---------------- launch -------------------------------------------------------
extern "C" void kernel_launch(void* const* d_in, const int* in_sizes, int n_in,
                              void* d_out, int out_size)
{
    const float* hidden     = (const float*)d_in[0];
    const float* in_proj_w  = (const float*)d_in[1];
    const float* conv_w     = (const float*)d_in[2];
    const float* A_log      = (const float*)d_in[3];
    const float* dt_bias    = (const float*)d_in[4];
    const float* norm_w     = (const float*)d_in[5];
    const float* out_proj_w = (const float*)d_in[6];
    float* out = (float*)d_out;

    float *p_proj, *p_q, *p_k, *p_v, *p_g, *p_b, *p_core;
    float *p_u, *p_wk, *p_bq, *p_p, *p_r;
    __nv_bfloat16 *p_hh, *p_hl, *p_w1h, *p_w1l, *p_gh, *p_gl, *p_w2h, *p_w2l;
    cudaGetSymbolAddress((void**)&p_proj, g_proj);
    cudaGetSymbolAddress((void**)&p_q,    g_q);
    cudaGetSymbolAddress((void**)&p_k,    g_k);
    cudaGetSymbolAddress((void**)&p_v,    g_v);
    cudaGetSymbolAddress((void**)&p_g,    g_gdec);
    cudaGetSymbolAddress((void**)&p_b,    g_beta);
    cudaGetSymbolAddress((void**)&p_core, g_core);
    cudaGetSymbolAddress((void**)&p_u,    g_u);
    cudaGetSymbolAddress((void**)&p_wk,   g_Wk);
    cudaGetSymbolAddress((void**)&p_bq,   g_Bq);
    cudaGetSymbolAddress((void**)&p_p,    g_P);
    cudaGetSymbolAddress((void**)&p_r,    g_R);
    cudaGetSymbolAddress((void**)&p_hh,   g_hid_hi);
    cudaGetSymbolAddress((void**)&p_hl,   g_hid_lo);
    cudaGetSymbolAddress((void**)&p_w1h,  g_w1_hi);
    cudaGetSymbolAddress((void**)&p_w1l,  g_w1_lo);
    cudaGetSymbolAddress((void**)&p_gh,   g_gat_hi);
    cudaGetSymbolAddress((void**)&p_gl,   g_gat_lo);
    cudaGetSymbolAddress((void**)&p_w2h,  g_w2_hi);
    cudaGetSymbolAddress((void**)&p_w2l,  g_w2_lo);

    cudaFuncSetAttribute(gemm_b3_kernel,
                         cudaFuncAttributeMaxDynamicSharedMemorySize, GEMM_SMEM);
    cudaFuncSetAttribute(wy_kernel,
                         cudaFuncAttributeMaxDynamicSharedMemorySize, WY_SMEMF * 4);
    cudaFuncSetAttribute(chunkscan_kernel,
                         cudaFuncAttributeMaxDynamicSharedMemorySize, CS_SMEMF * 4);

    {
        size_t n = (size_t)LSEQ * HDIM;
        conv_hl_kernel<<<(unsigned)((n + 255) / 256), 256>>>(hidden, p_hh, p_hl, n);
    }
    convT_kernel<<<dim3(NPAD1 / 32, HDIM / 32), 256>>>(in_proj_w, p_w1h, p_w1l,
                                                       HDIM, NPROJ);
    convT_kernel<<<dim3(HDIM / 32, VAL_DIM / 32), 256>>>(out_proj_w, p_w2h, p_w2l,
                                                         VAL_DIM, HDIM);

    gemm_b3_kernel<<<dim3(NPAD1 / 128, LSEQ / 128), 256, GEMM_SMEM>>>(
        p_hh, p_hl, p_w1h, p_w1l, p_proj, LSEQ, NPROJ, HDIM);

    prep_kernel<<<LSEQ, 256>>>(p_proj, conv_w, A_log, dt_bias,
                               p_q, p_k, p_v, p_g, p_b);

    wy_kernel<<<NHV * NCHK, 256, WY_SMEMF * 4>>>(p_k, p_q, p_v, p_g, p_b,
                                                 p_u, p_wk, p_bq, p_p, p_r);

    chunkscan_kernel<<<NHV * 4, 256, CS_SMEMF * 4>>>(p_q, p_k, p_u, p_wk,
                                                     p_bq, p_p, p_r, p_core);

    normgate_kernel<<<LSEQ * NHV, 128>>>(p_core, p_proj, norm_w, p_gh, p_gl);

    gemm_b3_kernel<<<dim3(HDIM / 128, LSEQ / 128), 256, GEMM_SMEM>>>(
        p_gh, p_gl, p_w2h, p_w2l, out, LSEQ, HDIM, VAL_DIM);
}